// round 1
// baseline (speedup 1.0000x reference)
#include <cuda_runtime.h>

#define Hdim 128
#define HIDdim 512

// scratch (no allocations allowed)
__device__ float g_phi1[HIDdim];
__device__ float g_u[Hdim];
__device__ float g_c;
__device__ double g_sum;
__device__ unsigned long long g_maxkey;

// ---------------------------------------------------------------------------
// K1: phi1[j] = dot(W1[j,:], output[prev,:]) + b1[j]   (512 warp-dots)
// grid = 128 blocks x 128 threads (4 warps/block, 1 j per warp)
// Block 0 also zeroes the accumulators for this launch sequence.
// ---------------------------------------------------------------------------
__global__ void k_phi1(const float* __restrict__ feat,
                       const float* __restrict__ W1,
                       const float* __restrict__ b1,
                       const int*   __restrict__ prev)
{
    const int lane = threadIdx.x & 31;
    const int warp = threadIdx.x >> 5;
    const int j = blockIdx.x * 4 + warp;              // 0..511
    const int p = prev[0];

    const float4 w = ((const float4*)(W1 + (size_t)j * Hdim))[lane];
    const float4 x = ((const float4*)(feat + (size_t)p * Hdim))[lane];
    float d = fmaf(w.x, x.x, fmaf(w.y, x.y, fmaf(w.z, x.z, w.w * x.w)));
    d += __shfl_xor_sync(0xffffffffu, d, 16);
    d += __shfl_xor_sync(0xffffffffu, d, 8);
    d += __shfl_xor_sync(0xffffffffu, d, 4);
    d += __shfl_xor_sync(0xffffffffu, d, 2);
    d += __shfl_xor_sync(0xffffffffu, d, 1);
    if (lane == 0) g_phi1[j] = d + b1[j];

    if (blockIdx.x == 0) {
        if (threadIdx.x < Hdim) g_u[threadIdx.x] = 0.0f;
        if (threadIdx.x == 0) { g_c = 0.0f; g_sum = 0.0; g_maxkey = 0ull; }
    }
}

// ---------------------------------------------------------------------------
// K2: u[h] = sum_j phi1[j] * W2[j,h],  c = phi1 . b2
// grid = 32 blocks x 128 threads; block b handles j in [16b, 16b+16)
// ---------------------------------------------------------------------------
__global__ void k_u(const float* __restrict__ W2,
                    const float* __restrict__ b2)
{
    const int h  = threadIdx.x;
    const int j0 = blockIdx.x * 16;

    float acc = 0.0f;
#pragma unroll
    for (int jj = 0; jj < 16; jj++) {
        acc = fmaf(g_phi1[j0 + jj], W2[(size_t)(j0 + jj) * Hdim + h], acc);
    }
    atomicAdd(&g_u[h], acc);

    __shared__ float sc;
    if (h == 0) sc = 0.0f;
    __syncthreads();
    if (h < 16) atomicAdd(&sc, g_phi1[j0 + h] * b2[j0 + h]);
    __syncthreads();
    if (h == 0) atomicAdd(&g_c, sc);
}

// ---------------------------------------------------------------------------
// K3 (main, HBM-bound): one warp per node, skip row load when adj==0.
// attn = 10*tanh((u.x_n + c)/sqrt(512));  sum exp(attn) (masked -> exp(0)=1)
// track max attn (attn!=0 only) + first index via packed 64-bit atomicMax.
// ---------------------------------------------------------------------------
__global__ void __launch_bounds__(256) k_main(const float* __restrict__ feat,
                                              const float* __restrict__ adj,
                                              int N)
{
    __shared__ float              ssum[8];
    __shared__ unsigned long long skey[8];

    const int lane  = threadIdx.x & 31;
    const int wwarp = threadIdx.x >> 5;
    const int gwarp = blockIdx.x * 8 + wwarp;
    const int nwarp = gridDim.x * 8;

    const float4 u4 = ((const float4*)g_u)[lane];
    const float  c  = g_c;

    float lsum = 0.0f;
    unsigned long long lkey = 0ull;

    for (int n = gwarp; n < N; n += nwarp) {
        const float a = __ldg(adj + n);
        if (a != 0.0f) {
            const float4 x = ((const float4*)feat)[(size_t)n * 32 + lane];
            float d = fmaf(u4.x, x.x, fmaf(u4.y, x.y, fmaf(u4.z, x.z, u4.w * x.w)));
            d += __shfl_xor_sync(0xffffffffu, d, 16);
            d += __shfl_xor_sync(0xffffffffu, d, 8);
            d += __shfl_xor_sync(0xffffffffu, d, 4);
            d += __shfl_xor_sync(0xffffffffu, d, 2);
            d += __shfl_xor_sync(0xffffffffu, d, 1);
            if (lane == 0) {
                const float s    = (d + c) * 0.04419417382415922f; // 1/sqrt(512)
                const float attn = 10.0f * tanhf(s);
                lsum += expf(attn);
                if (attn != 0.0f) {
                    unsigned b   = __float_as_uint(attn);
                    unsigned enc = (b & 0x80000000u) ? ~b : (b | 0x80000000u);
                    unsigned long long key =
                        ((unsigned long long)enc << 32) |
                        (unsigned long long)(0xFFFFFFFFu - (unsigned)n);
                    if (key > lkey) lkey = key;
                }
            }
        } else if (lane == 0) {
            lsum += 1.0f;   // exp(0) for masked node
        }
    }

    if (lane == 0) { ssum[wwarp] = lsum; skey[wwarp] = lkey; }
    __syncthreads();
    if (threadIdx.x == 0) {
        float bs = 0.0f;
        unsigned long long bk = 0ull;
#pragma unroll
        for (int i = 0; i < 8; i++) {
            bs += ssum[i];
            if (skey[i] > bk) bk = skey[i];
        }
        atomicAdd(&g_sum, (double)bs);
        atomicMax(&g_maxkey, bk);
    }
}

// ---------------------------------------------------------------------------
// K4: finalize -> out[0] = selected_node, out[1] = p
// ---------------------------------------------------------------------------
__global__ void k_fin(float* __restrict__ out, int out_size)
{
    const unsigned long long k = g_maxkey;
    float pidx = 0.0f, pval = 0.0f;
    if (k != 0ull) {
        const unsigned enc = (unsigned)(k >> 32);
        const unsigned b   = (enc & 0x80000000u) ? (enc ^ 0x80000000u) : ~enc;
        const float amax   = __uint_as_float(b);
        const int   idx    = (int)(0xFFFFFFFFu - (unsigned)(k & 0xFFFFFFFFull));
        pidx = (float)idx;
        pval = (float)(exp((double)amax) / g_sum);
    }
    out[0] = pidx;
    if (out_size > 1) out[1] = pval;
}

// ---------------------------------------------------------------------------
// inputs (metadata order): output[N,128], adj[N], W1[512,128], b1[512],
//                          W2[512,128], b2[512], prev_node (int scalar)
// ---------------------------------------------------------------------------
extern "C" void kernel_launch(void* const* d_in, const int* in_sizes, int n_in,
                              void* d_out, int out_size)
{
    const float* feat = (const float*)d_in[0];
    const float* adj  = (const float*)d_in[1];
    const float* W1   = (const float*)d_in[2];
    const float* b1   = (const float*)d_in[3];
    const float* W2   = (const float*)d_in[4];
    const float* b2   = (const float*)d_in[5];
    const int*   prev = (const int*)d_in[6];
    float* out = (float*)d_out;

    const int N = in_sizes[1];   // adj has N elements

    k_phi1<<<128, 128>>>(feat, W1, b1, prev);
    k_u<<<32, 128>>>(W2, b2);
    k_main<<<1184, 256>>>(feat, adj, N);
    k_fin<<<1, 1>>>(out, out_size);
}